// round 1
// baseline (speedup 1.0000x reference)
#include <cuda_runtime.h>

// MHSA with RPE bias.  B=256, N=196, C=784, H=4, D=196.
// Round 0: correct fp32 tiled-GEMM pipeline. Tensorization comes later.

namespace {
constexpr int B_ = 256, N_ = 196, C_ = 784, H_ = 4, D_ = 196;
constexpr int M_ = B_ * N_;  // 50176 rows for the projections
}

// Scratch (device globals: allocation-free per harness rules)
__device__ float g_q[B_ * H_ * N_ * D_];   // (b,h,n,d)
__device__ float g_k[B_ * H_ * N_ * D_];
__device__ float g_v[B_ * H_ * N_ * D_];
__device__ float g_s[B_ * H_ * N_ * N_];   // scores / attn
__device__ float g_ao[B_ * N_ * C_];       // attention output, merged heads
__device__ float g_cp[H_ * N_ * D_];       // rel_h + rel_w reshaped: cp[h][p][t]

// ---------------------------------------------------------------------------
// Projection GEMM (NT): out[row,col] = sum_k A[row,k] * W[col,k] + bias[col]
// M=50176 (div by 64), N=K=784.  sel: 0->g_q 1->g_k 2->g_v (split-head store),
// 3 -> plain store to `out`.  asel: 1 -> read A from g_ao.
// ---------------------------------------------------------------------------
__global__ __launch_bounds__(256) void proj_gemm(const float* __restrict__ A,
                                                 const float* __restrict__ W,
                                                 const float* __restrict__ bias,
                                                 float* __restrict__ out,
                                                 int sel, int asel) {
    constexpr int BM = 64, BN = 64, BK = 16;
    __shared__ float As[BM][BK + 1];
    __shared__ float Bs[BN][BK + 1];

    const float* __restrict__ Ap = (asel == 1) ? g_ao : A;

    const int t  = threadIdx.x;
    const int ty = t >> 4, tx = t & 15;
    const int m0 = blockIdx.y * BM;
    const int n0 = blockIdx.x * BN;

    const int lr  = t >> 2;        // 0..63 (tile row for loads)
    const int lc4 = (t & 3) * 4;   // 0,4,8,12

    float acc[4][4] = {};

    for (int k0 = 0; k0 < C_; k0 += BK) {
        float4 av = *reinterpret_cast<const float4*>(&Ap[(size_t)(m0 + lr) * C_ + k0 + lc4]);
        As[lr][lc4 + 0] = av.x; As[lr][lc4 + 1] = av.y;
        As[lr][lc4 + 2] = av.z; As[lr][lc4 + 3] = av.w;

        const int wrow = n0 + lr;
        float4 bv = make_float4(0.f, 0.f, 0.f, 0.f);
        if (wrow < C_)
            bv = *reinterpret_cast<const float4*>(&W[(size_t)wrow * C_ + k0 + lc4]);
        Bs[lr][lc4 + 0] = bv.x; Bs[lr][lc4 + 1] = bv.y;
        Bs[lr][lc4 + 2] = bv.z; Bs[lr][lc4 + 3] = bv.w;

        __syncthreads();
#pragma unroll
        for (int kk = 0; kk < BK; kk++) {
            float a[4], b[4];
#pragma unroll
            for (int i = 0; i < 4; i++) a[i] = As[ty * 4 + i][kk];
#pragma unroll
            for (int j = 0; j < 4; j++) b[j] = Bs[tx * 4 + j][kk];
#pragma unroll
            for (int i = 0; i < 4; i++)
#pragma unroll
                for (int j = 0; j < 4; j++) acc[i][j] += a[i] * b[j];
        }
        __syncthreads();
    }

#pragma unroll
    for (int i = 0; i < 4; i++) {
        const int row = m0 + ty * 4 + i;
        const int bb = row / N_, nn = row % N_;
#pragma unroll
        for (int j = 0; j < 4; j++) {
            const int col = n0 + tx * 4 + j;
            if (col >= C_) continue;
            const float v = acc[i][j] + bias[col];
            if (sel == 3) {
                out[(size_t)row * C_ + col] = v;
            } else {
                float* dst = (sel == 0) ? g_q : (sel == 1) ? g_k : g_v;
                const int hh = col / D_, dd = col % D_;
                dst[(((size_t)bb * H_ + hh) * N_ + nn) * D_ + dd] = v;
            }
        }
    }
}

// ---------------------------------------------------------------------------
// cp[h][p][t] = rel_h[h][t][p/14] + rel_w[h][t][p%14]
// ---------------------------------------------------------------------------
__global__ void build_cp(const float* __restrict__ rel_h,
                         const float* __restrict__ rel_w) {
    const int i = blockIdx.x * blockDim.x + threadIdx.x;
    if (i >= H_ * N_ * D_) return;
    const int t = i % D_;
    const int p = (i / D_) % N_;
    const int h = i / (D_ * N_);
    const int gh = p / 14, gw = p % 14;
    g_cp[i] = rel_h[(h * D_ + t) * 14 + gh] + rel_w[(h * D_ + t) * 14 + gw];
}

// ---------------------------------------------------------------------------
// Scores: S[n,m] = (1/14) * sum_d Q[n,d]K[m,d]  +  sum_t CP[n,t]Q[t,m]
// One block = 64x64 tile of one (b,h) score matrix. grid (4,4,1024).
// ---------------------------------------------------------------------------
__global__ __launch_bounds__(256) void scores_kernel() {
    constexpr int BM = 64, BN = 64, BK = 28;  // 196 = 7*28 exact K tiling
    __shared__ float As[BK][BM + 1];
    __shared__ float Bs[BK][BN + 1];

    const int bz = blockIdx.z;            // b*H + h
    const int h  = bz & (H_ - 1);
    const float* __restrict__ Q  = g_q  + (size_t)bz * N_ * D_;
    const float* __restrict__ Kp = g_k  + (size_t)bz * N_ * D_;
    const float* __restrict__ CP = g_cp + (size_t)h * N_ * D_;

    const int n0 = blockIdx.y * BM;
    const int m0 = blockIdx.x * BN;
    const int t = threadIdx.x, ty = t >> 4, tx = t & 15;

    float acc[4][4] = {};

    // ---- term 1: Q K^T (NT) ----
    for (int k0 = 0; k0 < D_; k0 += BK) {
        for (int i = t; i < BM * BK; i += 256) {
            const int r = i / BK, kk = i % BK, n = n0 + r;
            As[kk][r] = (n < N_) ? Q[(size_t)n * D_ + k0 + kk] : 0.f;
        }
        for (int i = t; i < BN * BK; i += 256) {
            const int r = i / BK, kk = i % BK, m = m0 + r;
            Bs[kk][r] = (m < N_) ? Kp[(size_t)m * D_ + k0 + kk] : 0.f;
        }
        __syncthreads();
#pragma unroll
        for (int kk = 0; kk < BK; kk++) {
            float a[4], b[4];
#pragma unroll
            for (int i = 0; i < 4; i++) a[i] = As[kk][ty * 4 + i];
#pragma unroll
            for (int j = 0; j < 4; j++) b[j] = Bs[kk][tx * 4 + j];
#pragma unroll
            for (int i = 0; i < 4; i++)
#pragma unroll
                for (int j = 0; j < 4; j++) acc[i][j] += a[i] * b[j];
        }
        __syncthreads();
    }

    constexpr float scale = 1.0f / 14.0f;
#pragma unroll
    for (int i = 0; i < 4; i++)
#pragma unroll
        for (int j = 0; j < 4; j++) acc[i][j] *= scale;

    // ---- term 2: CP @ Q (NN) ----
    for (int k0 = 0; k0 < N_; k0 += BK) {
        for (int i = t; i < BM * BK; i += 256) {
            const int r = i / BK, kk = i % BK, n = n0 + r;
            As[kk][r] = (n < N_) ? CP[(size_t)n * D_ + k0 + kk] : 0.f;
        }
        for (int i = t; i < BK * BN; i += 256) {
            const int kk = i / BN, c = i % BN, m = m0 + c;
            Bs[kk][c] = (m < N_) ? Q[(size_t)(k0 + kk) * D_ + m] : 0.f;
        }
        __syncthreads();
#pragma unroll
        for (int kk = 0; kk < BK; kk++) {
            float a[4], b[4];
#pragma unroll
            for (int i = 0; i < 4; i++) a[i] = As[kk][ty * 4 + i];
#pragma unroll
            for (int j = 0; j < 4; j++) b[j] = Bs[kk][tx * 4 + j];
#pragma unroll
            for (int i = 0; i < 4; i++)
#pragma unroll
                for (int j = 0; j < 4; j++) acc[i][j] += a[i] * b[j];
        }
        __syncthreads();
    }

    float* __restrict__ S = g_s + (size_t)bz * N_ * N_;
#pragma unroll
    for (int i = 0; i < 4; i++) {
        const int n = n0 + ty * 4 + i;
        if (n >= N_) continue;
#pragma unroll
        for (int j = 0; j < 4; j++) {
            const int m = m0 + tx * 4 + j;
            if (m < N_) S[(size_t)n * N_ + m] = acc[i][j];
        }
    }
}

// ---------------------------------------------------------------------------
// Row softmax over 196 elements; one warp per row, 8 rows/block.
// ---------------------------------------------------------------------------
__global__ __launch_bounds__(256) void softmax_kernel() {
    const int w = blockIdx.x * 8 + (threadIdx.x >> 5);
    const int lane = threadIdx.x & 31;
    if (w >= B_ * H_ * N_) return;
    float* __restrict__ row = g_s + (size_t)w * N_;

    float v[7];
    float mx = -3.4e38f;
#pragma unroll
    for (int i = 0; i < 7; i++) {
        const int c = lane + i * 32;
        v[i] = (c < N_) ? row[c] : -3.4e38f;
        mx = fmaxf(mx, v[i]);
    }
#pragma unroll
    for (int o = 16; o; o >>= 1) mx = fmaxf(mx, __shfl_xor_sync(0xffffffffu, mx, o));

    float s = 0.f;
#pragma unroll
    for (int i = 0; i < 7; i++) {
        const int c = lane + i * 32;
        v[i] = (c < N_) ? __expf(v[i] - mx) : 0.f;
        s += v[i];
    }
#pragma unroll
    for (int o = 16; o; o >>= 1) s += __shfl_xor_sync(0xffffffffu, s, o);
    const float inv = 1.0f / s;

#pragma unroll
    for (int i = 0; i < 7; i++) {
        const int c = lane + i * 32;
        if (c < N_) row[c] = v[i] * inv;
    }
}

// ---------------------------------------------------------------------------
// O = A @ V (NN) per (b,h); stores merged-head layout into g_ao.
// ---------------------------------------------------------------------------
__global__ __launch_bounds__(256) void av_kernel() {
    constexpr int BM = 64, BN = 64, BK = 28;
    __shared__ float As[BK][BM + 1];
    __shared__ float Bs[BK][BN + 1];

    const int bz = blockIdx.z;
    const int b = bz >> 2, h = bz & 3;
    const float* __restrict__ A = g_s + (size_t)bz * N_ * N_;
    const float* __restrict__ V = g_v + (size_t)bz * N_ * D_;

    const int n0 = blockIdx.y * BM;
    const int d0 = blockIdx.x * BN;
    const int t = threadIdx.x, ty = t >> 4, tx = t & 15;

    float acc[4][4] = {};
    for (int k0 = 0; k0 < N_; k0 += BK) {
        for (int i = t; i < BM * BK; i += 256) {
            const int r = i / BK, kk = i % BK, n = n0 + r;
            As[kk][r] = (n < N_) ? A[(size_t)n * N_ + k0 + kk] : 0.f;
        }
        for (int i = t; i < BK * BN; i += 256) {
            const int kk = i / BN, c = i % BN, d = d0 + c;
            Bs[kk][c] = (d < D_) ? V[(size_t)(k0 + kk) * D_ + d] : 0.f;
        }
        __syncthreads();
#pragma unroll
        for (int kk = 0; kk < BK; kk++) {
            float a[4], bq[4];
#pragma unroll
            for (int i = 0; i < 4; i++) a[i] = As[kk][ty * 4 + i];
#pragma unroll
            for (int j = 0; j < 4; j++) bq[j] = Bs[kk][tx * 4 + j];
#pragma unroll
            for (int i = 0; i < 4; i++)
#pragma unroll
                for (int j = 0; j < 4; j++) acc[i][j] += a[i] * bq[j];
        }
        __syncthreads();
    }

#pragma unroll
    for (int i = 0; i < 4; i++) {
        const int n = n0 + ty * 4 + i;
        if (n >= N_) continue;
#pragma unroll
        for (int j = 0; j < 4; j++) {
            const int d = d0 + tx * 4 + j;
            if (d < D_)
                g_ao[((size_t)b * N_ + n) * C_ + h * D_ + d] = acc[i][j];
        }
    }
}

// ---------------------------------------------------------------------------
extern "C" void kernel_launch(void* const* d_in, const int* in_sizes, int n_in,
                              void* d_out, int out_size) {
    const float* x  = (const float*)d_in[0];
    const float* Wq = (const float*)d_in[1];
    const float* bq = (const float*)d_in[2];
    const float* Wk = (const float*)d_in[3];
    const float* bk = (const float*)d_in[4];
    const float* Wv = (const float*)d_in[5];
    const float* bv = (const float*)d_in[6];
    const float* Wo = (const float*)d_in[7];
    const float* bo = (const float*)d_in[8];
    const float* rh = (const float*)d_in[9];
    const float* rw = (const float*)d_in[10];
    float* out = (float*)d_out;

    dim3 gproj((C_ + 63) / 64, M_ / 64);
    proj_gemm<<<gproj, 256>>>(x, Wq, bq, nullptr, 0, 0);
    proj_gemm<<<gproj, 256>>>(x, Wk, bk, nullptr, 1, 0);
    proj_gemm<<<gproj, 256>>>(x, Wv, bv, nullptr, 2, 0);

    build_cp<<<(H_ * N_ * D_ + 255) / 256, 256>>>(rh, rw);

    dim3 gatt(4, 4, B_ * H_);
    scores_kernel<<<gatt, 256>>>();

    softmax_kernel<<<(B_ * H_ * N_ + 7) / 8, 256>>>();

    av_kernel<<<gatt, 256>>>();

    proj_gemm<<<gproj, 256>>>(nullptr, Wo, bo, out, 3, 1);
}

// round 3
// speedup vs baseline: 1.2464x; 1.2464x over previous
#include <cuda_runtime.h>

// MHSA with RPE bias.  B=256, N=196, C=784, H=4, D=196.
// Round 3: all GEMMs on 3xTF32 split-precision mma.sync.m16n8k8.
//          a*b ~= ah*bh + ah*bl + al*bh  (effective ~fp32 inputs)

namespace {
constexpr int B_ = 256, N_ = 196, C_ = 784, H_ = 4, D_ = 196;
constexpr int M_ = B_ * N_;  // 50176
}

__device__ float g_q[B_ * H_ * N_ * D_];   // (b,h,n,d)
__device__ float g_k[B_ * H_ * N_ * D_];
__device__ float g_v[B_ * H_ * N_ * D_];
__device__ float g_s[B_ * H_ * N_ * N_];   // scores / attn
__device__ float g_ao[B_ * N_ * C_];       // attention out, merged heads
__device__ float g_cp[H_ * N_ * D_];       // cp[h][p][t]

__device__ __forceinline__ unsigned f2tf(float f) {
    unsigned u;
    asm("cvt.rna.tf32.f32 %0, %1;" : "=r"(u) : "f"(f));
    return u;
}
__device__ __forceinline__ void split_tf(float f, unsigned& h, unsigned& l) {
    h = f2tf(f);
    l = f2tf(f - __uint_as_float(h));
}

__device__ __forceinline__ void mma_tf32(float c[4], const unsigned a[4],
                                         const unsigned b[2]) {
    asm volatile(
        "mma.sync.aligned.m16n8k8.row.col.f32.tf32.tf32.f32 "
        "{%0,%1,%2,%3},{%4,%5,%6,%7},{%8,%9},{%0,%1,%2,%3};"
        : "+f"(c[0]), "+f"(c[1]), "+f"(c[2]), "+f"(c[3])
        : "r"(a[0]), "r"(a[1]), "r"(a[2]), "r"(a[3]), "r"(b[0]), "r"(b[1]));
}
// c += ah*bh + ah*bl + al*bh
__device__ __forceinline__ void mma3(float c[4], const unsigned ah[4],
                                     const unsigned al[4], const unsigned bh[2],
                                     const unsigned bl[2]) {
    mma_tf32(c, al, bh);
    mma_tf32(c, ah, bl);
    mma_tf32(c, ah, bh);
}

// ---------------------------------------------------------------------------
// Projection GEMM (NT): out[row,col] = sum_k A[row,k]*W[col,k] + bias[col]
// BM=128 BN=64 BK=16; 8 warps 4(M)x2(N), warp tile 32x32.
// sel: 0->g_q 1->g_k 2->g_v (split-head), 3 -> out.   asel 1: A = g_ao.
// ---------------------------------------------------------------------------
__global__ __launch_bounds__(256) void proj_mma(const float* __restrict__ A,
                                                const float* __restrict__ W,
                                                const float* __restrict__ bias,
                                                float* __restrict__ out,
                                                int sel, int asel) {
    __shared__ unsigned Ah[128][20], Al[128][20];
    __shared__ unsigned Bh[64][20],  Bl[64][20];

    const float* __restrict__ Ap = (asel == 1) ? g_ao : A;

    const int tid = threadIdx.x;
    const int wid = tid >> 5, lane = tid & 31;
    const int g = lane >> 2, tig = lane & 3;
    const int wm = wid & 3, wn = wid >> 2;
    const int m0 = blockIdx.y * 128;
    const int n0 = blockIdx.x * 64;

    const int lr = tid >> 2;       // 0..63
    const int lq = (tid & 3) * 4;  // 0,4,8,12

    float c[2][4][4] = {};

    for (int k0 = 0; k0 < C_; k0 += 16) {
        float4 a0 = *reinterpret_cast<const float4*>(&Ap[(size_t)(m0 + lr) * C_ + k0 + lq]);
        float4 a1 = *reinterpret_cast<const float4*>(&Ap[(size_t)(m0 + 64 + lr) * C_ + k0 + lq]);
        float4 wv = make_float4(0.f, 0.f, 0.f, 0.f);
        if (n0 + lr < C_)
            wv = *reinterpret_cast<const float4*>(&W[(size_t)(n0 + lr) * C_ + k0 + lq]);

        split_tf(a0.x, Ah[lr][lq + 0], Al[lr][lq + 0]);
        split_tf(a0.y, Ah[lr][lq + 1], Al[lr][lq + 1]);
        split_tf(a0.z, Ah[lr][lq + 2], Al[lr][lq + 2]);
        split_tf(a0.w, Ah[lr][lq + 3], Al[lr][lq + 3]);
        split_tf(a1.x, Ah[64 + lr][lq + 0], Al[64 + lr][lq + 0]);
        split_tf(a1.y, Ah[64 + lr][lq + 1], Al[64 + lr][lq + 1]);
        split_tf(a1.z, Ah[64 + lr][lq + 2], Al[64 + lr][lq + 2]);
        split_tf(a1.w, Ah[64 + lr][lq + 3], Al[64 + lr][lq + 3]);
        split_tf(wv.x, Bh[lr][lq + 0], Bl[lr][lq + 0]);
        split_tf(wv.y, Bh[lr][lq + 1], Bl[lr][lq + 1]);
        split_tf(wv.z, Bh[lr][lq + 2], Bl[lr][lq + 2]);
        split_tf(wv.w, Bh[lr][lq + 3], Bl[lr][lq + 3]);
        __syncthreads();

#pragma unroll
        for (int ks = 0; ks < 16; ks += 8) {
            unsigned ah[2][4], al[2][4], bh[4][2], bl[4][2];
#pragma unroll
            for (int mt = 0; mt < 2; mt++) {
                const int rb = wm * 32 + mt * 16;
                ah[mt][0] = Ah[rb + g][ks + tig];
                ah[mt][1] = Ah[rb + g + 8][ks + tig];
                ah[mt][2] = Ah[rb + g][ks + tig + 4];
                ah[mt][3] = Ah[rb + g + 8][ks + tig + 4];
                al[mt][0] = Al[rb + g][ks + tig];
                al[mt][1] = Al[rb + g + 8][ks + tig];
                al[mt][2] = Al[rb + g][ks + tig + 4];
                al[mt][3] = Al[rb + g + 8][ks + tig + 4];
            }
#pragma unroll
            for (int nt = 0; nt < 4; nt++) {
                const int cb = wn * 32 + nt * 8;
                bh[nt][0] = Bh[cb + g][ks + tig];
                bh[nt][1] = Bh[cb + g][ks + tig + 4];
                bl[nt][0] = Bl[cb + g][ks + tig];
                bl[nt][1] = Bl[cb + g][ks + tig + 4];
            }
#pragma unroll
            for (int mt = 0; mt < 2; mt++)
#pragma unroll
                for (int nt = 0; nt < 4; nt++)
                    mma3(c[mt][nt], ah[mt], al[mt], bh[nt], bl[nt]);
        }
        __syncthreads();
    }

#pragma unroll
    for (int mt = 0; mt < 2; mt++) {
#pragma unroll
        for (int nt = 0; nt < 4; nt++) {
#pragma unroll
            for (int e = 0; e < 4; e++) {
                const int row = m0 + wm * 32 + mt * 16 + g + (e >> 1) * 8;
                const int col = n0 + wn * 32 + nt * 8 + 2 * tig + (e & 1);
                if (col >= C_) continue;
                const float v = c[mt][nt][e] + bias[col];
                if (sel == 3) {
                    out[(size_t)row * C_ + col] = v;
                } else {
                    float* dst = (sel == 0) ? g_q : (sel == 1) ? g_k : g_v;
                    const int bb = row / N_, nn = row % N_;
                    const int hh = col / D_, dd = col % D_;
                    dst[(((size_t)bb * H_ + hh) * N_ + nn) * D_ + dd] = v;
                }
            }
        }
    }
}

// ---------------------------------------------------------------------------
__global__ void build_cp(const float* __restrict__ rel_h,
                         const float* __restrict__ rel_w) {
    const int i = blockIdx.x * blockDim.x + threadIdx.x;
    if (i >= H_ * N_ * D_) return;
    const int t = i % D_;
    const int p = (i / D_) % N_;
    const int h = i / (D_ * N_);
    g_cp[i] = rel_h[(h * D_ + t) * 14 + p / 14] + rel_w[(h * D_ + t) * 14 + p % 14];
}

// ---------------------------------------------------------------------------
// Scores: S[n,m] = (1/14) sum_d Q[n,d]K[m,d] + sum_t CP[n,t]Q[t,m]
// 64x64 tile per block; 8 warps 4(M)x2(N), warp tile 16x32.
// ---------------------------------------------------------------------------
__global__ __launch_bounds__(256) void scores_mma() {
    __shared__ unsigned Ahs[64][20], Als[64][20];    // [m][k]
    __shared__ unsigned Bhs[64][20], Bls[64][20];    // term1 [n][k]
    __shared__ unsigned B2h[16][68], B2l[16][68];    // term2 [k][n]

    const int bz = blockIdx.z;
    const int h = bz & (H_ - 1);
    const float* __restrict__ Q  = g_q  + (size_t)bz * N_ * D_;
    const float* __restrict__ Kp = g_k  + (size_t)bz * N_ * D_;
    const float* __restrict__ CP = g_cp + (size_t)h * N_ * D_;

    const int n0 = blockIdx.y * 64;
    const int m0 = blockIdx.x * 64;
    const int tid = threadIdx.x;
    const int wid = tid >> 5, lane = tid & 31;
    const int g = lane >> 2, tig = lane & 3;
    const int wm = wid & 3, wn = wid >> 2;

    const int lr = tid >> 2, lq = (tid & 3) * 4;
    const int lk = tid >> 4, lc = (tid & 15) * 4;

    float c[4][4] = {};
    constexpr float scale = 1.0f / 14.0f;

    // ---- term 1: (1/14) Q K^T (NT) ----
    for (int k0 = 0; k0 < 208; k0 += 16) {
        float4 qv = make_float4(0.f, 0.f, 0.f, 0.f);
        float4 kv = make_float4(0.f, 0.f, 0.f, 0.f);
        if (n0 + lr < N_ && k0 + lq < D_)
            qv = *reinterpret_cast<const float4*>(&Q[(size_t)(n0 + lr) * D_ + k0 + lq]);
        if (m0 + lr < N_ && k0 + lq < D_)
            kv = *reinterpret_cast<const float4*>(&Kp[(size_t)(m0 + lr) * D_ + k0 + lq]);
        split_tf(qv.x * scale, Ahs[lr][lq + 0], Als[lr][lq + 0]);
        split_tf(qv.y * scale, Ahs[lr][lq + 1], Als[lr][lq + 1]);
        split_tf(qv.z * scale, Ahs[lr][lq + 2], Als[lr][lq + 2]);
        split_tf(qv.w * scale, Ahs[lr][lq + 3], Als[lr][lq + 3]);
        split_tf(kv.x, Bhs[lr][lq + 0], Bls[lr][lq + 0]);
        split_tf(kv.y, Bhs[lr][lq + 1], Bls[lr][lq + 1]);
        split_tf(kv.z, Bhs[lr][lq + 2], Bls[lr][lq + 2]);
        split_tf(kv.w, Bhs[lr][lq + 3], Bls[lr][lq + 3]);
        __syncthreads();
#pragma unroll
        for (int ks = 0; ks < 16; ks += 8) {
            unsigned ah[4], al[4], bh[4][2], bl[4][2];
            const int rb = wm * 16;
            ah[0] = Ahs[rb + g][ks + tig];     al[0] = Als[rb + g][ks + tig];
            ah[1] = Ahs[rb + g + 8][ks + tig]; al[1] = Als[rb + g + 8][ks + tig];
            ah[2] = Ahs[rb + g][ks + tig + 4]; al[2] = Als[rb + g][ks + tig + 4];
            ah[3] = Ahs[rb + g + 8][ks + tig + 4]; al[3] = Als[rb + g + 8][ks + tig + 4];
#pragma unroll
            for (int nt = 0; nt < 4; nt++) {
                const int cb = wn * 32 + nt * 8;
                bh[nt][0] = Bhs[cb + g][ks + tig];
                bh[nt][1] = Bhs[cb + g][ks + tig + 4];
                bl[nt][0] = Bls[cb + g][ks + tig];
                bl[nt][1] = Bls[cb + g][ks + tig + 4];
            }
#pragma unroll
            for (int nt = 0; nt < 4; nt++) mma3(c[nt], ah, al, bh[nt], bl[nt]);
        }
        __syncthreads();
    }

    // ---- term 2: CP @ Q (NN) ----
    for (int k0 = 0; k0 < 208; k0 += 16) {
        float4 av = make_float4(0.f, 0.f, 0.f, 0.f);
        float4 bv = make_float4(0.f, 0.f, 0.f, 0.f);
        if (n0 + lr < N_ && k0 + lq < D_)
            av = *reinterpret_cast<const float4*>(&CP[(size_t)(n0 + lr) * D_ + k0 + lq]);
        if (k0 + lk < N_ && m0 + lc < D_)
            bv = *reinterpret_cast<const float4*>(&Q[(size_t)(k0 + lk) * D_ + m0 + lc]);
        split_tf(av.x, Ahs[lr][lq + 0], Als[lr][lq + 0]);
        split_tf(av.y, Ahs[lr][lq + 1], Als[lr][lq + 1]);
        split_tf(av.z, Ahs[lr][lq + 2], Als[lr][lq + 2]);
        split_tf(av.w, Ahs[lr][lq + 3], Als[lr][lq + 3]);
        split_tf(bv.x, B2h[lk][lc + 0], B2l[lk][lc + 0]);
        split_tf(bv.y, B2h[lk][lc + 1], B2l[lk][lc + 1]);
        split_tf(bv.z, B2h[lk][lc + 2], B2l[lk][lc + 2]);
        split_tf(bv.w, B2h[lk][lc + 3], B2l[lk][lc + 3]);
        __syncthreads();
#pragma unroll
        for (int ks = 0; ks < 16; ks += 8) {
            unsigned ah[4], al[4], bh[4][2], bl[4][2];
            const int rb = wm * 16;
            ah[0] = Ahs[rb + g][ks + tig];     al[0] = Als[rb + g][ks + tig];
            ah[1] = Ahs[rb + g + 8][ks + tig]; al[1] = Als[rb + g + 8][ks + tig];
            ah[2] = Ahs[rb + g][ks + tig + 4]; al[2] = Als[rb + g][ks + tig + 4];
            ah[3] = Ahs[rb + g + 8][ks + tig + 4]; al[3] = Als[rb + g + 8][ks + tig + 4];
#pragma unroll
            for (int nt = 0; nt < 4; nt++) {
                const int cb = wn * 32 + nt * 8;
                bh[nt][0] = B2h[ks + tig][cb + g];
                bh[nt][1] = B2h[ks + tig + 4][cb + g];
                bl[nt][0] = B2l[ks + tig][cb + g];
                bl[nt][1] = B2l[ks + tig + 4][cb + g];
            }
#pragma unroll
            for (int nt = 0; nt < 4; nt++) mma3(c[nt], ah, al, bh[nt], bl[nt]);
        }
        __syncthreads();
    }

    float* __restrict__ S = g_s + (size_t)bz * N_ * N_;
#pragma unroll
    for (int nt = 0; nt < 4; nt++) {
#pragma unroll
        for (int e = 0; e < 4; e++) {
            const int n = n0 + wm * 16 + g + (e >> 1) * 8;
            const int m = m0 + wn * 32 + nt * 8 + 2 * tig + (e & 1);
            if (n < N_ && m < N_) S[(size_t)n * N_ + m] = c[nt][e];
        }
    }
}

// ---------------------------------------------------------------------------
__global__ __launch_bounds__(256) void softmax_kernel() {
    const int w = blockIdx.x * 8 + (threadIdx.x >> 5);
    const int lane = threadIdx.x & 31;
    if (w >= B_ * H_ * N_) return;
    float* __restrict__ row = g_s + (size_t)w * N_;

    float v[7];
    float mx = -3.4e38f;
#pragma unroll
    for (int i = 0; i < 7; i++) {
        const int cc = lane + i * 32;
        v[i] = (cc < N_) ? row[cc] : -3.4e38f;
        mx = fmaxf(mx, v[i]);
    }
#pragma unroll
    for (int o = 16; o; o >>= 1) mx = fmaxf(mx, __shfl_xor_sync(0xffffffffu, mx, o));
    float s = 0.f;
#pragma unroll
    for (int i = 0; i < 7; i++) {
        const int cc = lane + i * 32;
        v[i] = (cc < N_) ? __expf(v[i] - mx) : 0.f;
        s += v[i];
    }
#pragma unroll
    for (int o = 16; o; o >>= 1) s += __shfl_xor_sync(0xffffffffu, s, o);
    const float inv = 1.0f / s;
#pragma unroll
    for (int i = 0; i < 7; i++) {
        const int cc = lane + i * 32;
        if (cc < N_) row[cc] = v[i] * inv;
    }
}

// ---------------------------------------------------------------------------
// O = A @ V (NN) per (b,h); merged-head store into g_ao.
// ---------------------------------------------------------------------------
__global__ __launch_bounds__(256) void av_mma() {
    __shared__ unsigned Ahs[64][20], Als[64][20];  // [n][k]
    __shared__ unsigned B2h[16][68], B2l[16][68];  // [k][d]

    const int bz = blockIdx.z;
    const int b = bz >> 2, h = bz & 3;
    const float* __restrict__ A = g_s + (size_t)bz * N_ * N_;
    const float* __restrict__ V = g_v + (size_t)bz * N_ * D_;

    const int n0 = blockIdx.y * 64;
    const int d0 = blockIdx.x * 64;
    const int tid = threadIdx.x;
    const int wid = tid >> 5, lane = tid & 31;
    const int g = lane >> 2, tig = lane & 3;
    const int wm = wid & 3, wn = wid >> 2;

    const int lr = tid >> 2, lq = (tid & 3) * 4;
    const int lk = tid >> 4, lc = (tid & 15) * 4;

    float c[4][4] = {};

    for (int k0 = 0; k0 < 208; k0 += 16) {
        float4 av = make_float4(0.f, 0.f, 0.f, 0.f);
        float4 bv = make_float4(0.f, 0.f, 0.f, 0.f);
        if (n0 + lr < N_ && k0 + lq < N_)
            av = *reinterpret_cast<const float4*>(&A[(size_t)(n0 + lr) * N_ + k0 + lq]);
        if (k0 + lk < N_ && d0 + lc < D_)
            bv = *reinterpret_cast<const float4*>(&V[(size_t)(k0 + lk) * D_ + d0 + lc]);
        split_tf(av.x, Ahs[lr][lq + 0], Als[lr][lq + 0]);
        split_tf(av.y, Ahs[lr][lq + 1], Als[lr][lq + 1]);
        split_tf(av.z, Ahs[lr][lq + 2], Als[lr][lq + 2]);
        split_tf(av.w, Ahs[lr][lq + 3], Als[lr][lq + 3]);
        split_tf(bv.x, B2h[lk][lc + 0], B2l[lk][lc + 0]);
        split_tf(bv.y, B2h[lk][lc + 1], B2l[lk][lc + 1]);
        split_tf(bv.z, B2h[lk][lc + 2], B2l[lk][lc + 2]);
        split_tf(bv.w, B2h[lk][lc + 3], B2l[lk][lc + 3]);
        __syncthreads();
#pragma unroll
        for (int ks = 0; ks < 16; ks += 8) {
            unsigned ah[4], al[4], bh[4][2], bl[4][2];
            const int rb = wm * 16;
            ah[0] = Ahs[rb + g][ks + tig];     al[0] = Als[rb + g][ks + tig];
            ah[1] = Ahs[rb + g + 8][ks + tig]; al[1] = Als[rb + g + 8][ks + tig];
            ah[2] = Ahs[rb + g][ks + tig + 4]; al[2] = Als[rb + g][ks + tig + 4];
            ah[3] = Ahs[rb + g + 8][ks + tig + 4]; al[3] = Als[rb + g + 8][ks + tig + 4];
#pragma unroll
            for (int nt = 0; nt < 4; nt++) {
                const int cb = wn * 32 + nt * 8;
                bh[nt][0] = B2h[ks + tig][cb + g];
                bh[nt][1] = B2h[ks + tig + 4][cb + g];
                bl[nt][0] = B2l[ks + tig][cb + g];
                bl[nt][1] = B2l[ks + tig + 4][cb + g];
            }
#pragma unroll
            for (int nt = 0; nt < 4; nt++) mma3(c[nt], ah, al, bh[nt], bl[nt]);
        }
        __syncthreads();
    }

#pragma unroll
    for (int nt = 0; nt < 4; nt++) {
#pragma unroll
        for (int e = 0; e < 4; e++) {
            const int n = n0 + wm * 16 + g + (e >> 1) * 8;
            const int d = d0 + wn * 32 + nt * 8 + 2 * tig + (e & 1);
            if (n < N_ && d < D_)
                g_ao[((size_t)b * N_ + n) * C_ + h * D_ + d] = c[nt][e];
        }
    }
}

// ---------------------------------------------------------------------------
extern "C" void kernel_launch(void* const* d_in, const int* in_sizes, int n_in,
                              void* d_out, int out_size) {
    const float* x  = (const float*)d_in[0];
    const float* Wq = (const float*)d_in[1];
    const float* bq = (const float*)d_in[2];
    const float* Wk = (const float*)d_in[3];
    const float* bk = (const float*)d_in[4];
    const float* Wv = (const float*)d_in[5];
    const float* bv = (const float*)d_in[6];
    const float* Wo = (const float*)d_in[7];
    const float* bo = (const float*)d_in[8];
    const float* rh = (const float*)d_in[9];
    const float* rw = (const float*)d_in[10];
    float* out = (float*)d_out;

    dim3 gproj((C_ + 63) / 64, M_ / 128);
    proj_mma<<<gproj, 256>>>(x, Wq, bq, nullptr, 0, 0);
    proj_mma<<<gproj, 256>>>(x, Wk, bk, nullptr, 1, 0);
    proj_mma<<<gproj, 256>>>(x, Wv, bv, nullptr, 2, 0);

    build_cp<<<(H_ * N_ * D_ + 255) / 256, 256>>>(rh, rw);

    dim3 gatt(4, 4, B_ * H_);
    scores_mma<<<gatt, 256>>>();
    softmax_kernel<<<(B_ * H_ * N_ + 7) / 8, 256>>>();
    av_mma<<<gatt, 256>>>();

    proj_mma<<<gproj, 256>>>(nullptr, Wo, bo, out, 3, 1);
}

// round 4
// speedup vs baseline: 2.0871x; 1.6745x over previous
#include <cuda_runtime.h>
#include <cuda_bf16.h>

// MHSA with RPE bias.  B=256, N=196, C=784, H=4, D=196.
// Round 4: split-bf16 (bf16x3) GEMMs on mma.sync.m16n8k16.
//          a*b ~= ah*bh + ah*bl + al*bh, effective ~16-bit mantissa inputs.

namespace {
constexpr int B_ = 256, N_ = 196, C_ = 784, H_ = 4, D_ = 196;
constexpr int M_ = B_ * N_;  // 50176
}

__device__ float g_q[B_ * H_ * N_ * D_];   // (b,h,n,d)
__device__ float g_k[B_ * H_ * N_ * D_];
__device__ float g_v[B_ * H_ * N_ * D_];
__device__ float g_s[B_ * H_ * N_ * N_];   // scores / attn
__device__ float g_ao[B_ * N_ * C_];       // attention out, merged heads
__device__ float g_cp[H_ * N_ * D_];       // cp[h][p][t]

__device__ __forceinline__ void split_bf(float f, unsigned short& h,
                                         unsigned short& l) {
    __nv_bfloat16 hb = __float2bfloat16(f);
    h = __bfloat16_as_ushort(hb);
    l = __bfloat16_as_ushort(__float2bfloat16(f - __bfloat162float(hb)));
}
// pack two consecutive-k values into one b32 (lo half = first element)
__device__ __forceinline__ void split2(float x, float y, unsigned& hi,
                                       unsigned& lo) {
    unsigned short hx, lx, hy, ly;
    split_bf(x, hx, lx);
    split_bf(y, hy, ly);
    hi = (unsigned)hx | ((unsigned)hy << 16);
    lo = (unsigned)lx | ((unsigned)ly << 16);
}

__device__ __forceinline__ void mma_bf16(float c[4], const unsigned a[4],
                                         const unsigned b[2]) {
    asm volatile(
        "mma.sync.aligned.m16n8k16.row.col.f32.bf16.bf16.f32 "
        "{%0,%1,%2,%3},{%4,%5,%6,%7},{%8,%9},{%0,%1,%2,%3};"
        : "+f"(c[0]), "+f"(c[1]), "+f"(c[2]), "+f"(c[3])
        : "r"(a[0]), "r"(a[1]), "r"(a[2]), "r"(a[3]), "r"(b[0]), "r"(b[1]));
}
__device__ __forceinline__ void mma3(float c[4], const unsigned ah[4],
                                     const unsigned al[4], const unsigned bh[2],
                                     const unsigned bl[2]) {
    mma_bf16(c, ah, bl);
    mma_bf16(c, al, bh);
    mma_bf16(c, ah, bh);
}

// ---------------------------------------------------------------------------
// Projection GEMM (NT): out[row,col] = sum_k A[row,k]*W[col,k] + bias[col]
// BM=128 BN=64 BK=16; 8 warps 4(M)x2(N), warp tile 32x32.
// Packed pair layout: X[row][k2], k2 = k/2, stride 12 (conflict-free).
// sel: 0->g_q 1->g_k 2->g_v (split-head), 3 -> out.   asel 1: A = g_ao.
// ---------------------------------------------------------------------------
__global__ __launch_bounds__(256) void proj_mma(const float* __restrict__ A,
                                                const float* __restrict__ W,
                                                const float* __restrict__ bias,
                                                float* __restrict__ out,
                                                int sel, int asel) {
    __shared__ unsigned Ah[128][12], Al[128][12];
    __shared__ unsigned Bh[64][12], Bl[64][12];

    const float* __restrict__ Ap = (asel == 1) ? g_ao : A;

    const int tid = threadIdx.x;
    const int wid = tid >> 5, lane = tid & 31;
    const int g = lane >> 2, tig = lane & 3;
    const int wm = wid & 3, wn = wid >> 2;
    const int m0 = blockIdx.y * 128;
    const int n0 = blockIdx.x * 64;

    const int lr = tid >> 2;         // 0..63
    const int lq = (tid & 3) * 4;    // k offset 0,4,8,12
    const int k2 = (tid & 3) * 2;    // packed index

    float c[2][4][4] = {};

    for (int k0 = 0; k0 < C_; k0 += 16) {
        float4 a0 = *reinterpret_cast<const float4*>(&Ap[(size_t)(m0 + lr) * C_ + k0 + lq]);
        float4 a1 = *reinterpret_cast<const float4*>(&Ap[(size_t)(m0 + 64 + lr) * C_ + k0 + lq]);
        float4 wv = make_float4(0.f, 0.f, 0.f, 0.f);
        if (n0 + lr < C_)
            wv = *reinterpret_cast<const float4*>(&W[(size_t)(n0 + lr) * C_ + k0 + lq]);

        split2(a0.x, a0.y, Ah[lr][k2], Al[lr][k2]);
        split2(a0.z, a0.w, Ah[lr][k2 + 1], Al[lr][k2 + 1]);
        split2(a1.x, a1.y, Ah[64 + lr][k2], Al[64 + lr][k2]);
        split2(a1.z, a1.w, Ah[64 + lr][k2 + 1], Al[64 + lr][k2 + 1]);
        split2(wv.x, wv.y, Bh[lr][k2], Bl[lr][k2]);
        split2(wv.z, wv.w, Bh[lr][k2 + 1], Bl[lr][k2 + 1]);
        __syncthreads();

        unsigned ah[2][4], al[2][4], bh[4][2], bl[4][2];
#pragma unroll
        for (int mt = 0; mt < 2; mt++) {
            const int rb = wm * 32 + mt * 16;
            ah[mt][0] = Ah[rb + g][tig];     al[mt][0] = Al[rb + g][tig];
            ah[mt][1] = Ah[rb + g + 8][tig]; al[mt][1] = Al[rb + g + 8][tig];
            ah[mt][2] = Ah[rb + g][tig + 4]; al[mt][2] = Al[rb + g][tig + 4];
            ah[mt][3] = Ah[rb + g + 8][tig + 4]; al[mt][3] = Al[rb + g + 8][tig + 4];
        }
#pragma unroll
        for (int nt = 0; nt < 4; nt++) {
            const int cb = wn * 32 + nt * 8;
            bh[nt][0] = Bh[cb + g][tig];     bl[nt][0] = Bl[cb + g][tig];
            bh[nt][1] = Bh[cb + g][tig + 4]; bl[nt][1] = Bl[cb + g][tig + 4];
        }
#pragma unroll
        for (int mt = 0; mt < 2; mt++)
#pragma unroll
            for (int nt = 0; nt < 4; nt++)
                mma3(c[mt][nt], ah[mt], al[mt], bh[nt], bl[nt]);
        __syncthreads();
    }

#pragma unroll
    for (int mt = 0; mt < 2; mt++) {
#pragma unroll
        for (int nt = 0; nt < 4; nt++) {
#pragma unroll
            for (int e = 0; e < 4; e++) {
                const int row = m0 + wm * 32 + mt * 16 + g + (e >> 1) * 8;
                const int col = n0 + wn * 32 + nt * 8 + 2 * tig + (e & 1);
                if (col >= C_) continue;
                const float v = c[mt][nt][e] + bias[col];
                if (sel == 3) {
                    out[(size_t)row * C_ + col] = v;
                } else {
                    float* dst = (sel == 0) ? g_q : (sel == 1) ? g_k : g_v;
                    const int bb = row / N_, nn = row % N_;
                    const int hh = col / D_, dd = col % D_;
                    dst[(((size_t)bb * H_ + hh) * N_ + nn) * D_ + dd] = v;
                }
            }
        }
    }
}

// ---------------------------------------------------------------------------
__global__ void build_cp(const float* __restrict__ rel_h,
                         const float* __restrict__ rel_w) {
    const int i = blockIdx.x * blockDim.x + threadIdx.x;
    if (i >= H_ * N_ * D_) return;
    const int t = i % D_;
    const int p = (i / D_) % N_;
    const int h = i / (D_ * N_);
    g_cp[i] = rel_h[(h * D_ + t) * 14 + p / 14] + rel_w[(h * D_ + t) * 14 + p % 14];
}

// ---------------------------------------------------------------------------
// Scores: S[n,m] = (1/14) sum_d Q[n,d]K[m,d] + sum_t CP[n,t]Q[t,m]
// 64x64 tile; 8 warps 4(M)x2(N), warp tile 16x32.
// Term2 B held as bf16 [n][k] (stride 18 halves) for packed-pair reads.
// ---------------------------------------------------------------------------
__global__ __launch_bounds__(256) void scores_mma() {
    __shared__ unsigned Ahs[64][12], Als[64][12];     // [m][k2]
    __shared__ unsigned Bhs[64][12], Bls[64][12];     // term1 [n][k2]
    __shared__ __nv_bfloat16 B2h[64][18], B2l[64][18];  // term2 [n][k]

    const int bz = blockIdx.z;
    const int h = bz & (H_ - 1);
    const float* __restrict__ Q  = g_q  + (size_t)bz * N_ * D_;
    const float* __restrict__ Kp = g_k  + (size_t)bz * N_ * D_;
    const float* __restrict__ CP = g_cp + (size_t)h * N_ * D_;

    const int n0 = blockIdx.y * 64;
    const int m0 = blockIdx.x * 64;
    const int tid = threadIdx.x;
    const int wid = tid >> 5, lane = tid & 31;
    const int g = lane >> 2, tig = lane & 3;
    const int wm = wid & 3, wn = wid >> 2;

    const int lr = tid >> 2, lq = (tid & 3) * 4, k2 = (tid & 3) * 2;
    const int lk = tid >> 4, lc = (tid & 15) * 4;

    float c[4][4] = {};
    constexpr float scale = 1.0f / 14.0f;

    // ---- term 1: (1/14) Q K^T (NT) ----
    for (int k0 = 0; k0 < 208; k0 += 16) {
        float4 qv = make_float4(0.f, 0.f, 0.f, 0.f);
        float4 kv = make_float4(0.f, 0.f, 0.f, 0.f);
        if (n0 + lr < N_ && k0 + lq < D_)
            qv = *reinterpret_cast<const float4*>(&Q[(size_t)(n0 + lr) * D_ + k0 + lq]);
        if (m0 + lr < N_ && k0 + lq < D_)
            kv = *reinterpret_cast<const float4*>(&Kp[(size_t)(m0 + lr) * D_ + k0 + lq]);
        split2(qv.x * scale, qv.y * scale, Ahs[lr][k2], Als[lr][k2]);
        split2(qv.z * scale, qv.w * scale, Ahs[lr][k2 + 1], Als[lr][k2 + 1]);
        split2(kv.x, kv.y, Bhs[lr][k2], Bls[lr][k2]);
        split2(kv.z, kv.w, Bhs[lr][k2 + 1], Bls[lr][k2 + 1]);
        __syncthreads();

        unsigned ah[4], al[4], bh[4][2], bl[4][2];
        const int rb = wm * 16;
        ah[0] = Ahs[rb + g][tig];     al[0] = Als[rb + g][tig];
        ah[1] = Ahs[rb + g + 8][tig]; al[1] = Als[rb + g + 8][tig];
        ah[2] = Ahs[rb + g][tig + 4]; al[2] = Als[rb + g][tig + 4];
        ah[3] = Ahs[rb + g + 8][tig + 4]; al[3] = Als[rb + g + 8][tig + 4];
#pragma unroll
        for (int nt = 0; nt < 4; nt++) {
            const int cb = wn * 32 + nt * 8;
            bh[nt][0] = Bhs[cb + g][tig];     bl[nt][0] = Bls[cb + g][tig];
            bh[nt][1] = Bhs[cb + g][tig + 4]; bl[nt][1] = Bls[cb + g][tig + 4];
        }
#pragma unroll
        for (int nt = 0; nt < 4; nt++) mma3(c[nt], ah, al, bh[nt], bl[nt]);
        __syncthreads();
    }

    // ---- term 2: CP @ Q (NN) ----
    for (int k0 = 0; k0 < 208; k0 += 16) {
        float4 av = make_float4(0.f, 0.f, 0.f, 0.f);
        float4 bv = make_float4(0.f, 0.f, 0.f, 0.f);
        if (n0 + lr < N_ && k0 + lq < D_)
            av = *reinterpret_cast<const float4*>(&CP[(size_t)(n0 + lr) * D_ + k0 + lq]);
        if (k0 + lk < N_ && m0 + lc < D_)
            bv = *reinterpret_cast<const float4*>(&Q[(size_t)(k0 + lk) * D_ + m0 + lc]);
        split2(av.x, av.y, Ahs[lr][k2], Als[lr][k2]);
        split2(av.z, av.w, Ahs[lr][k2 + 1], Als[lr][k2 + 1]);
#pragma unroll
        for (int j = 0; j < 4; j++) {
            const float f = (&bv.x)[j];
            unsigned short hh_, ll_;
            split_bf(f, hh_, ll_);
            B2h[lc + j][lk] = __ushort_as_bfloat16(hh_);
            B2l[lc + j][lk] = __ushort_as_bfloat16(ll_);
        }
        __syncthreads();

        unsigned ah[4], al[4], bh[4][2], bl[4][2];
        const int rb = wm * 16;
        ah[0] = Ahs[rb + g][tig];     al[0] = Als[rb + g][tig];
        ah[1] = Ahs[rb + g + 8][tig]; al[1] = Als[rb + g + 8][tig];
        ah[2] = Ahs[rb + g][tig + 4]; al[2] = Als[rb + g][tig + 4];
        ah[3] = Ahs[rb + g + 8][tig + 4]; al[3] = Als[rb + g + 8][tig + 4];
#pragma unroll
        for (int nt = 0; nt < 4; nt++) {
            const int cb = wn * 32 + nt * 8;
            bh[nt][0] = *reinterpret_cast<const unsigned*>(&B2h[cb + g][2 * tig]);
            bh[nt][1] = *reinterpret_cast<const unsigned*>(&B2h[cb + g][2 * tig + 8]);
            bl[nt][0] = *reinterpret_cast<const unsigned*>(&B2l[cb + g][2 * tig]);
            bl[nt][1] = *reinterpret_cast<const unsigned*>(&B2l[cb + g][2 * tig + 8]);
        }
#pragma unroll
        for (int nt = 0; nt < 4; nt++) mma3(c[nt], ah, al, bh[nt], bl[nt]);
        __syncthreads();
    }

    float* __restrict__ S = g_s + (size_t)bz * N_ * N_;
#pragma unroll
    for (int nt = 0; nt < 4; nt++) {
#pragma unroll
        for (int e = 0; e < 4; e++) {
            const int n = n0 + wm * 16 + g + (e >> 1) * 8;
            const int m = m0 + wn * 32 + nt * 8 + 2 * tig + (e & 1);
            if (n < N_ && m < N_) S[(size_t)n * N_ + m] = c[nt][e];
        }
    }
}

// ---------------------------------------------------------------------------
__global__ __launch_bounds__(256) void softmax_kernel() {
    const int w = blockIdx.x * 8 + (threadIdx.x >> 5);
    const int lane = threadIdx.x & 31;
    if (w >= B_ * H_ * N_) return;
    float* __restrict__ row = g_s + (size_t)w * N_;

    float v[7];
    float mx = -3.4e38f;
#pragma unroll
    for (int i = 0; i < 7; i++) {
        const int cc = lane + i * 32;
        v[i] = (cc < N_) ? row[cc] : -3.4e38f;
        mx = fmaxf(mx, v[i]);
    }
#pragma unroll
    for (int o = 16; o; o >>= 1) mx = fmaxf(mx, __shfl_xor_sync(0xffffffffu, mx, o));
    float s = 0.f;
#pragma unroll
    for (int i = 0; i < 7; i++) {
        const int cc = lane + i * 32;
        v[i] = (cc < N_) ? __expf(v[i] - mx) : 0.f;
        s += v[i];
    }
#pragma unroll
    for (int o = 16; o; o >>= 1) s += __shfl_xor_sync(0xffffffffu, s, o);
    const float inv = 1.0f / s;
#pragma unroll
    for (int i = 0; i < 7; i++) {
        const int cc = lane + i * 32;
        if (cc < N_) row[cc] = v[i] * inv;
    }
}

// ---------------------------------------------------------------------------
// O = A @ V (NN) per (b,h); merged-head store into g_ao.
// ---------------------------------------------------------------------------
__global__ __launch_bounds__(256) void av_mma() {
    __shared__ unsigned Ahs[64][12], Als[64][12];       // [n][k2]
    __shared__ __nv_bfloat16 B2h[64][18], B2l[64][18];  // [d][k]

    const int bz = blockIdx.z;
    const int b = bz >> 2, h = bz & 3;
    const float* __restrict__ A = g_s + (size_t)bz * N_ * N_;
    const float* __restrict__ V = g_v + (size_t)bz * N_ * D_;

    const int n0 = blockIdx.y * 64;
    const int d0 = blockIdx.x * 64;
    const int tid = threadIdx.x;
    const int wid = tid >> 5, lane = tid & 31;
    const int g = lane >> 2, tig = lane & 3;
    const int wm = wid & 3, wn = wid >> 2;

    const int lr = tid >> 2, lq = (tid & 3) * 4, k2 = (tid & 3) * 2;
    const int lk = tid >> 4, lc = (tid & 15) * 4;

    float c[4][4] = {};

    for (int k0 = 0; k0 < 208; k0 += 16) {
        float4 av = make_float4(0.f, 0.f, 0.f, 0.f);
        float4 bv = make_float4(0.f, 0.f, 0.f, 0.f);
        if (n0 + lr < N_ && k0 + lq < N_)
            av = *reinterpret_cast<const float4*>(&A[(size_t)(n0 + lr) * N_ + k0 + lq]);
        if (k0 + lk < N_ && d0 + lc < D_)
            bv = *reinterpret_cast<const float4*>(&V[(size_t)(k0 + lk) * D_ + d0 + lc]);
        split2(av.x, av.y, Ahs[lr][k2], Als[lr][k2]);
        split2(av.z, av.w, Ahs[lr][k2 + 1], Als[lr][k2 + 1]);
#pragma unroll
        for (int j = 0; j < 4; j++) {
            const float f = (&bv.x)[j];
            unsigned short hh_, ll_;
            split_bf(f, hh_, ll_);
            B2h[lc + j][lk] = __ushort_as_bfloat16(hh_);
            B2l[lc + j][lk] = __ushort_as_bfloat16(ll_);
        }
        __syncthreads();

        unsigned ah[4], al[4], bh[4][2], bl[4][2];
        const int rb = wm * 16;
        ah[0] = Ahs[rb + g][tig];     al[0] = Als[rb + g][tig];
        ah[1] = Ahs[rb + g + 8][tig]; al[1] = Als[rb + g + 8][tig];
        ah[2] = Ahs[rb + g][tig + 4]; al[2] = Als[rb + g][tig + 4];
        ah[3] = Ahs[rb + g + 8][tig + 4]; al[3] = Als[rb + g + 8][tig + 4];
#pragma unroll
        for (int nt = 0; nt < 4; nt++) {
            const int cb = wn * 32 + nt * 8;
            bh[nt][0] = *reinterpret_cast<const unsigned*>(&B2h[cb + g][2 * tig]);
            bh[nt][1] = *reinterpret_cast<const unsigned*>(&B2h[cb + g][2 * tig + 8]);
            bl[nt][0] = *reinterpret_cast<const unsigned*>(&B2l[cb + g][2 * tig]);
            bl[nt][1] = *reinterpret_cast<const unsigned*>(&B2l[cb + g][2 * tig + 8]);
        }
#pragma unroll
        for (int nt = 0; nt < 4; nt++) mma3(c[nt], ah, al, bh[nt], bl[nt]);
        __syncthreads();
    }

#pragma unroll
    for (int nt = 0; nt < 4; nt++) {
#pragma unroll
        for (int e = 0; e < 4; e++) {
            const int n = n0 + wm * 16 + g + (e >> 1) * 8;
            const int d = d0 + wn * 32 + nt * 8 + 2 * tig + (e & 1);
            if (n < N_ && d < D_)
                g_ao[((size_t)b * N_ + n) * C_ + h * D_ + d] = c[nt][e];
        }
    }
}

// ---------------------------------------------------------------------------
extern "C" void kernel_launch(void* const* d_in, const int* in_sizes, int n_in,
                              void* d_out, int out_size) {
    const float* x  = (const float*)d_in[0];
    const float* Wq = (const float*)d_in[1];
    const float* bq = (const float*)d_in[2];
    const float* Wk = (const float*)d_in[3];
    const float* bk = (const float*)d_in[4];
    const float* Wv = (const float*)d_in[5];
    const float* bv = (const float*)d_in[6];
    const float* Wo = (const float*)d_in[7];
    const float* bo = (const float*)d_in[8];
    const float* rh = (const float*)d_in[9];
    const float* rw = (const float*)d_in[10];
    float* out = (float*)d_out;

    dim3 gproj((C_ + 63) / 64, M_ / 128);
    proj_mma<<<gproj, 256>>>(x, Wq, bq, nullptr, 0, 0);
    proj_mma<<<gproj, 256>>>(x, Wk, bk, nullptr, 1, 0);
    proj_mma<<<gproj, 256>>>(x, Wv, bv, nullptr, 2, 0);

    build_cp<<<(H_ * N_ * D_ + 255) / 256, 256>>>(rh, rw);

    dim3 gatt(4, 4, B_ * H_);
    scores_mma<<<gatt, 256>>>();
    softmax_kernel<<<(B_ * H_ * N_ + 7) / 8, 256>>>();
    av_mma<<<gatt, 256>>>();

    proj_mma<<<gproj, 256>>>(nullptr, Wo, bo, out, 3, 1);
}

// round 8
// speedup vs baseline: 2.3314x; 1.1170x over previous
#include <cuda_runtime.h>
#include <cuda_bf16.h>
#include <cstdint>

// MHSA with RPE bias.  B=256, N=196, C=784, H=4, D=196.
// Round 8: R7 with the missing K-tail guards in proj_mma2 fixed
// (784 % 32 == 16 — last BK=32 chunk must zero-fill k >= 784).

namespace {
constexpr int B_ = 256, N_ = 196, C_ = 784, H_ = 4, D_ = 196;
constexpr int M_ = B_ * N_;  // 50176
}

// ---- pre-split operand storage (bf16 hi / lo arrays, same logical layouts) --
__device__ __nv_bfloat16 g_xh[M_ * C_], g_xl[M_ * C_];          // x
__device__ __nv_bfloat16 g_wh[4 * C_ * C_], g_wl[4 * C_ * C_];  // Wq,Wk,Wv,Wo
__device__ __nv_bfloat16 g_qh[B_ * H_ * N_ * D_], g_ql[B_ * H_ * N_ * D_];
__device__ __nv_bfloat16 g_kh[B_ * H_ * N_ * D_], g_kl[B_ * H_ * N_ * D_];
__device__ __nv_bfloat16 g_vh[B_ * H_ * N_ * D_], g_vl[B_ * H_ * N_ * D_];
__device__ __nv_bfloat16 g_aoh[M_ * C_], g_aol[M_ * C_];        // attn out
__device__ __nv_bfloat16 g_cph[H_ * N_ * D_], g_cpl[H_ * N_ * D_];
__device__ float g_s[B_ * H_ * N_ * N_];                        // scores/probs

// ---- helpers ---------------------------------------------------------------
__device__ __forceinline__ void split_bf(float f, unsigned short& h,
                                         unsigned short& l) {
    __nv_bfloat16 hb = __float2bfloat16(f);
    h = __bfloat16_as_ushort(hb);
    l = __bfloat16_as_ushort(__float2bfloat16(f - __bfloat162float(hb)));
}
// split a,b and pack into one hi-uint and one lo-uint (a = low half)
__device__ __forceinline__ void split_pack(float a, float b, unsigned& H,
                                           unsigned& L) {
    unsigned short ha, la, hb, lb;
    split_bf(a, ha, la);
    split_bf(b, hb, lb);
    H = (unsigned)ha | ((unsigned)hb << 16);
    L = (unsigned)la | ((unsigned)lb << 16);
}

__device__ __forceinline__ void mma_bf16(float c[4], const unsigned a[4],
                                         const unsigned b[2]) {
    asm volatile(
        "mma.sync.aligned.m16n8k16.row.col.f32.bf16.bf16.f32 "
        "{%0,%1,%2,%3},{%4,%5,%6,%7},{%8,%9},{%0,%1,%2,%3};"
        : "+f"(c[0]), "+f"(c[1]), "+f"(c[2]), "+f"(c[3])
        : "r"(a[0]), "r"(a[1]), "r"(a[2]), "r"(a[3]), "r"(b[0]), "r"(b[1]));
}
__device__ __forceinline__ void mma3(float c[4], const unsigned ah[4],
                                     const unsigned al[4], const unsigned bh[2],
                                     const unsigned bl[2]) {
    mma_bf16(c, ah, bl);
    mma_bf16(c, al, bh);
    mma_bf16(c, ah, bh);
}

// ---------------------------------------------------------------------------
// split_arr: fp32 -> packed bf16 hi/lo.  dst_sel 0 -> x, 1..4 -> W slot
// ---------------------------------------------------------------------------
__global__ void split_arr(const float* __restrict__ src, int dst_sel, int n4) {
    const int i = blockIdx.x * blockDim.x + threadIdx.x;
    if (i >= n4) return;
    __nv_bfloat16 *dh, *dl;
    if (dst_sel == 0) { dh = g_xh; dl = g_xl; }
    else {
        dh = g_wh + (size_t)(dst_sel - 1) * C_ * C_;
        dl = g_wl + (size_t)(dst_sel - 1) * C_ * C_;
    }
    const float4 v = reinterpret_cast<const float4*>(src)[i];
    unsigned H0, L0, H1, L1;
    split_pack(v.x, v.y, H0, L0);
    split_pack(v.z, v.w, H1, L1);
    reinterpret_cast<uint2*>(dh)[i] = make_uint2(H0, H1);
    reinterpret_cast<uint2*>(dl)[i] = make_uint2(L0, L1);
}

// ---------------------------------------------------------------------------
// build_cp: cp[h][p][t] = rel_h[h][t][p/14] + rel_w[h][t][p%14], split-stored
// ---------------------------------------------------------------------------
__global__ void build_cp(const float* __restrict__ rel_h,
                         const float* __restrict__ rel_w) {
    const int i = blockIdx.x * blockDim.x + threadIdx.x;
    if (i >= H_ * N_ * D_) return;
    const int t = i % D_;
    const int p = (i / D_) % N_;
    const int h = i / (D_ * N_);
    const float v =
        rel_h[(h * D_ + t) * 14 + p / 14] + rel_w[(h * D_ + t) * 14 + p % 14];
    unsigned short hh, ll;
    split_bf(v, hh, ll);
    g_cph[i] = __ushort_as_bfloat16(hh);
    g_cpl[i] = __ushort_as_bfloat16(ll);
}

// ---------------------------------------------------------------------------
// Projection GEMM (NT): out[row,col] = sum_k A[row,k]*W[col,k] + bias[col]
// BM=128, BN=112 (7*112=784 exact), BK=32 (last chunk zero-padded: 784%32=16).
// 8 warps 4(M)x2(N); warp tile 32x56.
// sel 0/1/2 -> packed split store to q/k/v (b,h,n,d); 3 -> fp32 out.
// asel 1 -> A = attention output (pre-split).
// ---------------------------------------------------------------------------
__global__ __launch_bounds__(256) void proj_mma2(const float* __restrict__ bias,
                                                 float* __restrict__ out,
                                                 int widx, int sel, int asel) {
    __shared__ unsigned Ahs[128][20], Als[128][20];
    __shared__ unsigned Bhs[112][20], Bls[112][20];

    const __nv_bfloat16* __restrict__ Asrc_h = asel ? g_aoh : g_xh;
    const __nv_bfloat16* __restrict__ Asrc_l = asel ? g_aol : g_xl;
    const __nv_bfloat16* __restrict__ Wh = g_wh + (size_t)widx * C_ * C_;
    const __nv_bfloat16* __restrict__ Wl = g_wl + (size_t)widx * C_ * C_;

    const int tid = threadIdx.x;
    const int wid = tid >> 5, lane = tid & 31;
    const int g = lane >> 2, tig = lane & 3;
    const int wm = wid & 3, wn = wid >> 2;
    const int m0 = blockIdx.y * 128;
    const int n0 = blockIdx.x * 112;

    float c[2][7][4] = {};

    for (int k0 = 0; k0 < C_; k0 += 32) {
        // A: 128 rows x 32 k.  thread -> (row = tid/2, half = tid&1);
        // each half = 16 bf16 = 2 x uint4 per hi/lo array.  Zero-fill k >= C_.
        {
            const int row = tid >> 1, half = tid & 1;
            const int kk = k0 + half * 16;
            uint4 h0 = make_uint4(0, 0, 0, 0), h1 = make_uint4(0, 0, 0, 0);
            uint4 l0 = make_uint4(0, 0, 0, 0), l1 = make_uint4(0, 0, 0, 0);
            if (kk + 15 < C_) {
                const size_t e0 = (size_t)(m0 + row) * C_ + kk;
                h0 = *reinterpret_cast<const uint4*>(&Asrc_h[e0]);
                h1 = *reinterpret_cast<const uint4*>(&Asrc_h[e0 + 8]);
                l0 = *reinterpret_cast<const uint4*>(&Asrc_l[e0]);
                l1 = *reinterpret_cast<const uint4*>(&Asrc_l[e0 + 8]);
            }
            *reinterpret_cast<uint4*>(&Ahs[row][half * 8]) = h0;
            *reinterpret_cast<uint4*>(&Ahs[row][half * 8 + 4]) = h1;
            *reinterpret_cast<uint4*>(&Als[row][half * 8]) = l0;
            *reinterpret_cast<uint4*>(&Als[row][half * 8 + 4]) = l1;
        }
        // W: 112 rows x 32 k; unit = (row, quarter of 8 elems).  Zero-fill tail.
        for (int u = tid; u < 112 * 4; u += 256) {
            const int row = u >> 2, q = u & 3;
            const int kk = k0 + q * 8;
            uint4 hv = make_uint4(0, 0, 0, 0), lv = make_uint4(0, 0, 0, 0);
            if (kk + 7 < C_) {
                const size_t e0 = (size_t)(n0 + row) * C_ + kk;
                hv = *reinterpret_cast<const uint4*>(&Wh[e0]);
                lv = *reinterpret_cast<const uint4*>(&Wl[e0]);
            }
            *reinterpret_cast<uint4*>(&Bhs[row][q * 4]) = hv;
            *reinterpret_cast<uint4*>(&Bls[row][q * 4]) = lv;
        }
        __syncthreads();

#pragma unroll
        for (int ks = 0; ks < 2; ks++) {
            const int kb = ks * 8;
            unsigned ah[2][4], al[2][4];
#pragma unroll
            for (int mt = 0; mt < 2; mt++) {
                const int rb = wm * 32 + mt * 16;
                ah[mt][0] = Ahs[rb + g][kb + tig];
                ah[mt][1] = Ahs[rb + g + 8][kb + tig];
                ah[mt][2] = Ahs[rb + g][kb + tig + 4];
                ah[mt][3] = Ahs[rb + g + 8][kb + tig + 4];
                al[mt][0] = Als[rb + g][kb + tig];
                al[mt][1] = Als[rb + g + 8][kb + tig];
                al[mt][2] = Als[rb + g][kb + tig + 4];
                al[mt][3] = Als[rb + g + 8][kb + tig + 4];
            }
#pragma unroll
            for (int nt = 0; nt < 7; nt++) {
                const int cb = wn * 56 + nt * 8;
                unsigned bh[2], bl[2];
                bh[0] = Bhs[cb + g][kb + tig];
                bh[1] = Bhs[cb + g][kb + tig + 4];
                bl[0] = Bls[cb + g][kb + tig];
                bl[1] = Bls[cb + g][kb + tig + 4];
#pragma unroll
                for (int mt = 0; mt < 2; mt++)
                    mma3(c[mt][nt], ah[mt], al[mt], bh, bl);
            }
        }
        __syncthreads();
    }

    // epilogue: column pairs (2*tig, 2*tig+1)
#pragma unroll
    for (int mt = 0; mt < 2; mt++) {
#pragma unroll
        for (int nt = 0; nt < 7; nt++) {
#pragma unroll
            for (int eh = 0; eh < 2; eh++) {
                const int row = m0 + wm * 32 + mt * 16 + g + eh * 8;
                const int col0 = n0 + wn * 56 + nt * 8 + 2 * tig;
                const float v0 = c[mt][nt][eh * 2 + 0] + bias[col0];
                const float v1 = c[mt][nt][eh * 2 + 1] + bias[col0 + 1];
                if (sel == 3) {
                    *reinterpret_cast<float2*>(&out[(size_t)row * C_ + col0]) =
                        make_float2(v0, v1);
                } else {
                    unsigned Hp, Lp;
                    split_pack(v0, v1, Hp, Lp);
                    const int bb = row / N_, nn = row % N_;
                    const int hh = col0 / D_, dd = col0 % D_;
                    const size_t off =
                        (((size_t)bb * H_ + hh) * N_ + nn) * D_ + dd;
                    __nv_bfloat16* dh =
                        (sel == 0) ? g_qh : (sel == 1) ? g_kh : g_vh;
                    __nv_bfloat16* dl =
                        (sel == 0) ? g_ql : (sel == 1) ? g_kl : g_vl;
                    *reinterpret_cast<unsigned*>(&dh[off]) = Hp;
                    *reinterpret_cast<unsigned*>(&dl[off]) = Lp;
                }
            }
        }
    }
}

// ---------------------------------------------------------------------------
// Scores: S = (1/14) Q K^T  +  CP @ Qt.   64x64 tiles, warp tile 16x32.
// ---------------------------------------------------------------------------
__global__ __launch_bounds__(256) void scores_mma() {
    __shared__ unsigned Ahs[64][12], Als[64][12];
    __shared__ unsigned Bhs[64][12], Bls[64][12];
    __shared__ __nv_bfloat16 B2h[64][18], B2l[64][18];

    const int bz = blockIdx.z;
    const int h = bz & (H_ - 1);
    const __nv_bfloat16* __restrict__ Qh = g_qh + (size_t)bz * N_ * D_;
    const __nv_bfloat16* __restrict__ Ql = g_ql + (size_t)bz * N_ * D_;
    const __nv_bfloat16* __restrict__ Kh = g_kh + (size_t)bz * N_ * D_;
    const __nv_bfloat16* __restrict__ Kl = g_kl + (size_t)bz * N_ * D_;
    const __nv_bfloat16* __restrict__ CPh = g_cph + (size_t)h * N_ * D_;
    const __nv_bfloat16* __restrict__ CPl = g_cpl + (size_t)h * N_ * D_;

    const int n0 = blockIdx.y * 64;
    const int m0 = blockIdx.x * 64;
    const int tid = threadIdx.x;
    const int wid = tid >> 5, lane = tid & 31;
    const int g = lane >> 2, tig = lane & 3;
    const int wm = wid & 3, wn = wid >> 2;

    const int lr = tid >> 2, lq = (tid & 3) * 4, k2 = (tid & 3) * 2;
    const int lk = tid >> 4, lc = (tid & 15) * 4;

    float c[4][4] = {};

    // ---- term 1: Q K^T (scale applied afterwards) ----
    for (int k0 = 0; k0 < 208; k0 += 16) {
        uint2 qh = make_uint2(0, 0), ql = make_uint2(0, 0);
        uint2 kh = make_uint2(0, 0), kl = make_uint2(0, 0);
        if (n0 + lr < N_ && k0 + lq + 3 < D_) {
            const size_t e = (size_t)(n0 + lr) * D_ + k0 + lq;
            qh = *reinterpret_cast<const uint2*>(&Qh[e]);
            ql = *reinterpret_cast<const uint2*>(&Ql[e]);
        }
        if (m0 + lr < N_ && k0 + lq + 3 < D_) {
            const size_t e = (size_t)(m0 + lr) * D_ + k0 + lq;
            kh = *reinterpret_cast<const uint2*>(&Kh[e]);
            kl = *reinterpret_cast<const uint2*>(&Kl[e]);
        }
        *reinterpret_cast<uint2*>(&Ahs[lr][k2]) = qh;
        *reinterpret_cast<uint2*>(&Als[lr][k2]) = ql;
        *reinterpret_cast<uint2*>(&Bhs[lr][k2]) = kh;
        *reinterpret_cast<uint2*>(&Bls[lr][k2]) = kl;
        __syncthreads();

        unsigned ah[4], al[4];
        const int rb = wm * 16;
        ah[0] = Ahs[rb + g][tig];     al[0] = Als[rb + g][tig];
        ah[1] = Ahs[rb + g + 8][tig]; al[1] = Als[rb + g + 8][tig];
        ah[2] = Ahs[rb + g][tig + 4]; al[2] = Als[rb + g][tig + 4];
        ah[3] = Ahs[rb + g + 8][tig + 4]; al[3] = Als[rb + g + 8][tig + 4];
#pragma unroll
        for (int nt = 0; nt < 4; nt++) {
            const int cb = wn * 32 + nt * 8;
            unsigned bh[2], bl[2];
            bh[0] = Bhs[cb + g][tig];     bl[0] = Bls[cb + g][tig];
            bh[1] = Bhs[cb + g][tig + 4]; bl[1] = Bls[cb + g][tig + 4];
            mma3(c[nt], ah, al, bh, bl);
        }
        __syncthreads();
    }

    constexpr float scale = 1.0f / 14.0f;
#pragma unroll
    for (int nt = 0; nt < 4; nt++)
#pragma unroll
        for (int e = 0; e < 4; e++) c[nt][e] *= scale;

    // ---- term 2: CP @ Q (B read transposed into [n][k] smem) ----
    for (int k0 = 0; k0 < 208; k0 += 16) {
        uint2 ch = make_uint2(0, 0), cl = make_uint2(0, 0);
        if (n0 + lr < N_ && k0 + lq + 3 < D_) {
            const size_t e = (size_t)(n0 + lr) * D_ + k0 + lq;
            ch = *reinterpret_cast<const uint2*>(&CPh[e]);
            cl = *reinterpret_cast<const uint2*>(&CPl[e]);
        }
        *reinterpret_cast<uint2*>(&Ahs[lr][k2]) = ch;
        *reinterpret_cast<uint2*>(&Als[lr][k2]) = cl;

        uint2 bh2 = make_uint2(0, 0), bl2 = make_uint2(0, 0);
        if (k0 + lk < N_ && m0 + lc + 3 < D_) {
            const size_t e = (size_t)(k0 + lk) * D_ + m0 + lc;
            bh2 = *reinterpret_cast<const uint2*>(&Qh[e]);
            bl2 = *reinterpret_cast<const uint2*>(&Ql[e]);
        }
        {
            const __nv_bfloat16* ph = reinterpret_cast<const __nv_bfloat16*>(&bh2);
            const __nv_bfloat16* pl = reinterpret_cast<const __nv_bfloat16*>(&bl2);
#pragma unroll
            for (int j = 0; j < 4; j++) {
                B2h[lc + j][lk] = ph[j];
                B2l[lc + j][lk] = pl[j];
            }
        }
        __syncthreads();

        unsigned ah[4], al[4];
        const int rb = wm * 16;
        ah[0] = Ahs[rb + g][tig];     al[0] = Als[rb + g][tig];
        ah[1] = Ahs[rb + g + 8][tig]; al[1] = Als[rb + g + 8][tig];
        ah[2] = Ahs[rb + g][tig + 4]; al[2] = Als[rb + g][tig + 4];
        ah[3] = Ahs[rb + g + 8][tig + 4]; al[3] = Als[rb + g + 8][tig + 4];
#pragma unroll
        for (int nt = 0; nt < 4; nt++) {
            const int cb = wn * 32 + nt * 8;
            unsigned bh[2], bl[2];
            bh[0] = *reinterpret_cast<const unsigned*>(&B2h[cb + g][2 * tig]);
            bh[1] = *reinterpret_cast<const unsigned*>(&B2h[cb + g][2 * tig + 8]);
            bl[0] = *reinterpret_cast<const unsigned*>(&B2l[cb + g][2 * tig]);
            bl[1] = *reinterpret_cast<const unsigned*>(&B2l[cb + g][2 * tig + 8]);
            mma3(c[nt], ah, al, bh, bl);
        }
        __syncthreads();
    }

    float* __restrict__ S = g_s + (size_t)bz * N_ * N_;
#pragma unroll
    for (int nt = 0; nt < 4; nt++) {
#pragma unroll
        for (int eh = 0; eh < 2; eh++) {
            const int n = n0 + wm * 16 + g + eh * 8;
            const int m = m0 + wn * 32 + nt * 8 + 2 * tig;
            if (n < N_ && m < N_)
                *reinterpret_cast<float2*>(&S[(size_t)n * N_ + m]) =
                    make_float2(c[nt][eh * 2], c[nt][eh * 2 + 1]);
        }
    }
}

// ---------------------------------------------------------------------------
__global__ __launch_bounds__(256) void softmax_kernel() {
    const int w = blockIdx.x * 8 + (threadIdx.x >> 5);
    const int lane = threadIdx.x & 31;
    if (w >= B_ * H_ * N_) return;
    float* __restrict__ row = g_s + (size_t)w * N_;

    float v[7];
    float mx = -3.4e38f;
#pragma unroll
    for (int i = 0; i < 7; i++) {
        const int cc = lane + i * 32;
        v[i] = (cc < N_) ? row[cc] : -3.4e38f;
        mx = fmaxf(mx, v[i]);
    }
#pragma unroll
    for (int o = 16; o; o >>= 1) mx = fmaxf(mx, __shfl_xor_sync(0xffffffffu, mx, o));
    float s = 0.f;
#pragma unroll
    for (int i = 0; i < 7; i++) {
        const int cc = lane + i * 32;
        v[i] = (cc < N_) ? __expf(v[i] - mx) : 0.f;
        s += v[i];
    }
#pragma unroll
    for (int o = 16; o; o >>= 1) s += __shfl_xor_sync(0xffffffffu, s, o);
    const float inv = 1.0f / s;
#pragma unroll
    for (int i = 0; i < 7; i++) {
        const int cc = lane + i * 32;
        if (cc < N_) row[cc] = v[i] * inv;
    }
}

// ---------------------------------------------------------------------------
// O = A @ V; A = probs (fp32, split at load), V pre-split. Split store to ao.
// ---------------------------------------------------------------------------
__global__ __launch_bounds__(256) void av_mma() {
    __shared__ unsigned Ahs[64][12], Als[64][12];
    __shared__ __nv_bfloat16 B2h[64][18], B2l[64][18];

    const int bz = blockIdx.z;
    const int b = bz >> 2, h = bz & 3;
    const float* __restrict__ A = g_s + (size_t)bz * N_ * N_;
    const __nv_bfloat16* __restrict__ Vh = g_vh + (size_t)bz * N_ * D_;
    const __nv_bfloat16* __restrict__ Vl = g_vl + (size_t)bz * N_ * D_;

    const int n0 = blockIdx.y * 64;
    const int d0 = blockIdx.x * 64;
    const int tid = threadIdx.x;
    const int wid = tid >> 5, lane = tid & 31;
    const int g = lane >> 2, tig = lane & 3;
    const int wm = wid & 3, wn = wid >> 2;

    const int lr = tid >> 2, lq = (tid & 3) * 4, k2 = (tid & 3) * 2;
    const int lk = tid >> 4, lc = (tid & 15) * 4;

    float c[4][4] = {};

    for (int k0 = 0; k0 < 208; k0 += 16) {
        float4 av = make_float4(0.f, 0.f, 0.f, 0.f);
        if (n0 + lr < N_ && k0 + lq + 3 < N_)
            av = *reinterpret_cast<const float4*>(&A[(size_t)(n0 + lr) * N_ + k0 + lq]);
        split_pack(av.x, av.y, Ahs[lr][k2], Als[lr][k2]);
        split_pack(av.z, av.w, Ahs[lr][k2 + 1], Als[lr][k2 + 1]);

        uint2 bh2 = make_uint2(0, 0), bl2 = make_uint2(0, 0);
        if (k0 + lk < N_ && d0 + lc + 3 < D_) {
            const size_t e = (size_t)(k0 + lk) * D_ + d0 + lc;
            bh2 = *reinterpret_cast<const uint2*>(&Vh[e]);
            bl2 = *reinterpret_cast<const uint2*>(&Vl[e]);
        }
        {
            const __nv_bfloat16* ph = reinterpret_cast<const __nv_bfloat16*>(&bh2);
            const __nv_bfloat16* pl = reinterpret_cast<const __nv_bfloat16*>(&bl2);
#pragma unroll
            for (int j = 0; j < 4; j++) {
                B2h[lc + j][lk] = ph[j];
                B2l[lc + j][lk] = pl[j];
            }
        }
        __syncthreads();

        unsigned ah[4], al[4];
        const int rb = wm * 16;
        ah[0] = Ahs[rb + g][tig];     al[0] = Als[rb + g][tig];
        ah[1] = Ahs[rb + g + 8][tig]; al[1] = Als[rb + g + 8][tig];
        ah[2] = Ahs[rb + g][tig + 4]; al[2] = Als[rb + g][tig + 4];
        ah[3] = Ahs[rb + g + 8][tig + 4]; al[3] = Als[rb + g + 8][tig + 4];
#pragma unroll
        for (int nt = 0; nt < 4; nt++) {
            const int cb = wn * 32 + nt * 8;
            unsigned bh[2], bl[2];
            bh[0] = *reinterpret_cast<const unsigned*>(&B2h[cb + g][2 * tig]);
            bh[1] = *reinterpret_cast<const unsigned*>(&B2h[cb + g][2 * tig + 8]);
            bl[0] = *reinterpret_cast<const unsigned*>(&B2l[cb + g][2 * tig]);
            bl[1] = *reinterpret_cast<const unsigned*>(&B2l[cb + g][2 * tig + 8]);
            mma3(c[nt], ah, al, bh, bl);
        }
        __syncthreads();
    }

#pragma unroll
    for (int nt = 0; nt < 4; nt++) {
#pragma unroll
        for (int eh = 0; eh < 2; eh++) {
            const int n = n0 + wm * 16 + g + eh * 8;
            const int d = d0 + wn * 32 + nt * 8 + 2 * tig;
            if (n < N_ && d < D_) {
                unsigned Hp, Lp;
                split_pack(c[nt][eh * 2], c[nt][eh * 2 + 1], Hp, Lp);
                const size_t off = ((size_t)b * N_ + n) * C_ + h * D_ + d;
                *reinterpret_cast<unsigned*>(&g_aoh[off]) = Hp;
                *reinterpret_cast<unsigned*>(&g_aol[off]) = Lp;
            }
        }
    }
}

// ---------------------------------------------------------------------------
extern "C" void kernel_launch(void* const* d_in, const int* in_sizes, int n_in,
                              void* d_out, int out_size) {
    const float* x  = (const float*)d_in[0];
    const float* Wq = (const float*)d_in[1];
    const float* bq = (const float*)d_in[2];
    const float* Wk = (const float*)d_in[3];
    const float* bk = (const float*)d_in[4];
    const float* Wv = (const float*)d_in[5];
    const float* bv = (const float*)d_in[6];
    const float* Wo = (const float*)d_in[7];
    const float* bo = (const float*)d_in[8];
    const float* rh = (const float*)d_in[9];
    const float* rw = (const float*)d_in[10];
    float* out = (float*)d_out;

    const int n4x = M_ * C_ / 4;
    const int n4w = C_ * C_ / 4;
    split_arr<<<(n4x + 255) / 256, 256>>>(x, 0, n4x);
    split_arr<<<(n4w + 255) / 256, 256>>>(Wq, 1, n4w);
    split_arr<<<(n4w + 255) / 256, 256>>>(Wk, 2, n4w);
    split_arr<<<(n4w + 255) / 256, 256>>>(Wv, 3, n4w);
    split_arr<<<(n4w + 255) / 256, 256>>>(Wo, 4, n4w);

    build_cp<<<(H_ * N_ * D_ + 255) / 256, 256>>>(rh, rw);

    dim3 gproj(C_ / 112, M_ / 128);  // (7, 392)
    proj_mma2<<<gproj, 256>>>(bq, nullptr, 0, 0, 0);
    proj_mma2<<<gproj, 256>>>(bk, nullptr, 1, 1, 0);
    proj_mma2<<<gproj, 256>>>(bv, nullptr, 2, 2, 0);

    dim3 gatt(4, 4, B_ * H_);
    scores_mma<<<gatt, 256>>>();
    softmax_kernel<<<(B_ * H_ * N_ + 7) / 8, 256>>>();
    av_mma<<<gatt, 256>>>();

    proj_mma2<<<gproj, 256>>>(bo, out, 3, 3, 1);
}